// round 13
// baseline (speedup 1.0000x reference)
#include <cuda_runtime.h>
#include <cuda_fp16.h>
#include <cstdint>
#include <math.h>

// Problem dims
#define B_ROWS 8192
#define N_COLS 512
#define M_MIN  1024
#define OUT_N  256
#define K_TOT  4096   // 512*6 + 1024

// ---------------- device scratch (static, no allocation) ----------------
__device__ float g_psum[64 * 512];
__device__ float g_psumsq[64 * 512];
__device__ float g_s[512];
__device__ float g_dq[6 * 512];           // [q][n]  (q=0 base, q=1..5 branches)
__device__ uint32_t g_minidx[M_MIN];      // packed (off2<<16)|off1, off = q*512+n (< 3072)
__device__ __align__(16) __half g_wT[(size_t)OUT_N * K_TOT];   // 2 MB (B^T, [256,4096] K-major, K-permuted)

__constant__ float QCOEF[5] = {-3.0f, -0.834f, -0.248f, 0.248f, 0.834f};

// ---------------- helpers ----------------
__device__ __forceinline__ uint32_t smem_u32(const void* p) {
    uint32_t a;
    asm("{ .reg .u64 t; cvta.to.shared.u64 t, %1; cvt.u32.u64 %0, t; }"
        : "=r"(a) : "l"(p));
    return a;
}

// ---------------- stage 1: column statistics (deterministic two-pass) ----------------
__global__ void __launch_bounds__(512) k_stats(const float* __restrict__ x) {
    int col = threadIdx.x;
    int rb  = blockIdx.x * 128;
    const float* xp = x + (size_t)rb * 512 + col;
    float s = 0.f, ss = 0.f;
#pragma unroll 8
    for (int r = 0; r < 128; r++) {
        float v = xp[(size_t)r * 512];
        s += v;
        ss = fmaf(v, v, ss);
    }
    g_psum[blockIdx.x * 512 + col]   = s;
    g_psumsq[blockIdx.x * 512 + col] = ss;
}

// ---------------- stage 2: finalize stats + pack min indices (merged, 1 block) ----------------
// chosen_index may arrive as int64 OR int32 (JAX x64-disabled silently downcasts).
// Column 0 is arange(M): int32-view element 10 == 1 iff int64, == 2 iff int32.
__global__ void __launch_bounds__(1024) k_finalize(const float* __restrict__ beta,
                                                   const float* __restrict__ gamma,
                                                   const void* __restrict__ ci_raw) {
    int tid = threadIdx.x;
    if (tid < 512) {
        int n = tid;
        float s = 0.f, ss = 0.f;
        for (int b = 0; b < 64; b++) {       // fixed order -> deterministic
            s  += g_psum[b * 512 + n];
            ss += g_psumsq[b * 512 + n];
        }
        float mean = s * (1.f / 8192.f);
        float var  = ss * (1.f / 8192.f) - mean * mean;
        float sc   = gamma[n] / sqrtf(var + 0.001f);
        float c    = beta[n] - mean * sc;    // normed = sc*x + c
        g_s[n]  = sc;
        g_dq[n] = c;                          // q = 0 (base relu)
#pragma unroll
        for (int q = 0; q < 5; q++)
            g_dq[(q + 1) * 512 + n] = c + beta[n] - gamma[n] * fmaf(QCOEF[q], var, mean);
    }
    {
        int m = tid;
        const int* p32 = (const int*)ci_raw;
        bool is64 = (p32[10] == 1) && (p32[11] == 0);
        uint32_t n1, q1, n2, q2;
        if (is64) {
            const long long* e = (const long long*)ci_raw + (size_t)m * 5;
            n1 = (uint32_t)e[1]; q1 = (uint32_t)e[2];
            n2 = (uint32_t)e[3]; q2 = (uint32_t)e[4];
        } else {
            const int* e = p32 + (size_t)m * 5;
            n1 = (uint32_t)e[1]; q1 = (uint32_t)e[2];
            n2 = (uint32_t)e[3]; q2 = (uint32_t)e[4];
        }
        g_minidx[m] = ((q2 * 512u + n2) << 16) | (q1 * 512u + n1);
    }
}

// ---------------- stage 3: w -> wT fp16, K-permuted (j = q*512+n for j<3072) ----------------
__global__ void __launch_bounds__(256) k_wprep(const float* __restrict__ w) {
    __shared__ float tile[32][33];
    int j0 = blockIdx.x * 32, o0 = blockIdx.y * 32;
    int tx = threadIdx.x, ty = threadIdx.y;
    for (int i = ty; i < 32; i += 8) {
        int j = j0 + i;
        int k = (j < 3072) ? ((j & 511) * 6 + (j >> 9)) : j;   // back to original row order
        tile[i][tx] = w[(size_t)k * 256 + o0 + tx];
    }
    __syncthreads();
    for (int i = ty; i < 32; i += 8)
        g_wT[(size_t)(o0 + i) * K_TOT + j0 + tx] = __float2half_rn(tile[tx][i]);
}

// ---------------- stage 4: FUSED featgen + GEMM (512 threads, 16 warps) ----------------
// BM=64, BN=256, BK=64, grid=128 (one wave). A tile synthesized in smem from
// p[row][n] = x*s (fp16, stride 520 halfs, conflict-free); B via cp.async.
#define A_SLOT_BYTES  8192                      // 64 rows x 128 B
#define B_STAGE_BYTES 32768                     // 256 rows x 128 B
#define B_OFF   (2 * A_SLOT_BYTES)              // 16384
#define P_OFF   (B_OFF + 4 * B_STAGE_BYTES)     // 147456
#define P_STRIDE 520                            // halfs per p row
#define GEMM_SMEM (P_OFF + 64 * P_STRIDE * 2)   // 214016

__global__ void __launch_bounds__(512, 1) k_gemm(float* __restrict__ out,
                                                 const float* __restrict__ x,
                                                 const float* __restrict__ biases) {
    extern __shared__ __align__(1024) char smem[];
    uint32_t sb = smem_u32(smem);
    __half* p_sh = (__half*)(smem + P_OFF);
    int tid = threadIdx.x, wid = tid >> 5, lid = tid & 31;
    int r0 = blockIdx.x * 64;    // batch-row tile

    // warp tiling: 4 (M) x 4 (N): warp tile 16 (M) x 64 (N)
    int wm = (wid & 3) * 16;
    int wn = (wid >> 2) * 64;

    const char* Bbase = (const char*)g_wT;

    auto issueB = [&](int chunk, int stage) {
        uint32_t sB = sb + B_OFF + stage * B_STAGE_BYTES;
        const char* Bg = Bbase + chunk * 128;
#pragma unroll
        for (int t = 0; t < 4; t++) {
            int idx = tid + t * 512;            // 0..2047
            int row = idx >> 3, jj = idx & 7;
            uint32_t off = row * 128 + 16 * (jj ^ (row & 7));
            const char* gb = Bg + (size_t)row * 8192 + jj * 16;
            asm volatile("cp.async.cg.shared.global [%0], [%1], 16;\n"
                         :: "r"(sB + off), "l"(gb));
        }
    };

    // ---- A producer: synthesize 64x64 fp16 tile for K-chunk into A slot ----
    // 512 units: jj = tid&7 (16B group), row = tid>>3 (0..63)
    int jj = tid & 7, arow = tid >> 3;
    auto produceA = [&](int chunk, int slot) {
        char* sa = smem + slot * A_SLOT_BYTES;
        uint32_t dsto = arow * 128 + 16 * (jj ^ (arow & 7));
        if (chunk < 48) {
            int q = chunk >> 3;
            int nc = (chunk & 7) * 64 + jj * 8;          // p column base (0..511)
            const float4* dd = (const float4*)(g_dq + q * 512 + nc);
            float4 da = dd[0], db = dd[1];
            const __half2* pr = (const __half2*)(p_sh + arow * P_STRIDE + nc);
            __half2 h0 = pr[0], h1 = pr[1], h2 = pr[2], h3 = pr[3];
            float2 f0 = __half22float2(h0), f1 = __half22float2(h1);
            float2 f2 = __half22float2(h2), f3 = __half22float2(h3);
            union { __half2 h[4]; uint4 u; } o;
            o.h[0] = __floats2half2_rn(fmaxf(f0.x + da.x, 0.f), fmaxf(f0.y + da.y, 0.f));
            o.h[1] = __floats2half2_rn(fmaxf(f1.x + da.z, 0.f), fmaxf(f1.y + da.w, 0.f));
            o.h[2] = __floats2half2_rn(fmaxf(f2.x + db.x, 0.f), fmaxf(f2.y + db.y, 0.f));
            o.h[3] = __floats2half2_rn(fmaxf(f3.x + db.z, 0.f), fmaxf(f3.y + db.w, 0.f));
            *(uint4*)(sa + dsto) = o.u;
        } else {
            int m0 = (chunk - 48) * 64 + jj * 8;
            uint4 pa = *(const uint4*)(g_minidx + m0);
            uint4 pb = *(const uint4*)(g_minidx + m0 + 4);
            uint32_t pk[8] = {pa.x, pa.y, pa.z, pa.w, pb.x, pb.y, pb.z, pb.w};
            const __half* pr = p_sh + arow * P_STRIDE;
            union { __half2 h[4]; uint4 u; } o;
#pragma unroll
            for (int i = 0; i < 4; i++) {
                uint32_t wa = pk[2 * i], wb = pk[2 * i + 1];
                int a1 = wa & 0xFFFF, a2 = wa >> 16;
                int b1 = wb & 0xFFFF, b2 = wb >> 16;
                float va = fminf(fmaxf(__half2float(pr[a1 & 511]) + g_dq[a1], 0.f),
                                 fmaxf(__half2float(pr[a2 & 511]) + g_dq[a2], 0.f));
                float vb = fminf(fmaxf(__half2float(pr[b1 & 511]) + g_dq[b1], 0.f),
                                 fmaxf(__half2float(pr[b2 & 511]) + g_dq[b2], 0.f));
                o.h[i] = __floats2half2_rn(va, vb);
            }
            *(uint4*)(sa + dsto) = o.u;
        }
    };

    // ---- prefetch B ----
    issueB(0, 0); asm volatile("cp.async.commit_group;\n");
    issueB(1, 1); asm volatile("cp.async.commit_group;\n");
    issueB(2, 2); asm volatile("cp.async.commit_group;\n");

    // ---- build p[64][512]: p = x * s (fp16) ----
    {
        int grp = tid & 63;        // 8-float group within row
        int rt  = tid >> 6;        // 0..7
        const float4* s4 = (const float4*)(g_s + grp * 8);
        float4 sa4 = s4[0], sb4 = s4[1];
#pragma unroll
        for (int t = 0; t < 8; t++) {
            int row = rt + t * 8;
            const float4* xr = (const float4*)(x + (size_t)(r0 + row) * 512 + grp * 8);
            float4 xa = xr[0], xb = xr[1];
            union { __half2 h[4]; uint4 u; } o;
            o.h[0] = __floats2half2_rn(xa.x * sa4.x, xa.y * sa4.y);
            o.h[1] = __floats2half2_rn(xa.z * sa4.z, xa.w * sa4.w);
            o.h[2] = __floats2half2_rn(xb.x * sb4.x, xb.y * sb4.y);
            o.h[3] = __floats2half2_rn(xb.z * sb4.z, xb.w * sb4.w);
            *(uint4*)(p_sh + row * P_STRIDE + grp * 8) = o.u;
        }
    }
    __syncthreads();
    produceA(0, 0);                 // first A tile

    // per-lane ldmatrix address constants
    int l7 = lid & 7, mi = lid >> 3;
    int a_row = wm + (mi & 1) * 8 + l7;
    int a_jc  = mi >> 1;            // 0/1 within k16
    int b_row = wn + (mi >> 1) * 8 + l7;
    int b_jc  = mi & 1;

    float acc[8][4];
#pragma unroll
    for (int j = 0; j < 8; j++)
#pragma unroll
        for (int k = 0; k < 4; k++) acc[j][k] = 0.f;

    for (int chunk = 0; chunk < 64; chunk++) {
        asm volatile("cp.async.wait_group 2;\n");
        __syncthreads();            // B(chunk) + A(chunk) visible; prev A-slot reads done

        // produce A(chunk+1) FIRST so its LDS/STS latency hides under the MMAs
        if (chunk + 1 < 64)
            produceA(chunk + 1, (chunk + 1) & 1);

        uint32_t sA  = sb + (chunk & 1) * A_SLOT_BYTES;
        uint32_t sBB = sb + B_OFF + (chunk & 3) * B_STAGE_BYTES;

#pragma unroll
        for (int ks = 0; ks < 4; ks++) {        // 4 x k16 per BK=64 chunk
            uint32_t a[4];
            {
                int r = a_row;
                uint32_t addr = sA + r * 128 + 16 * ((ks * 2 + a_jc) ^ (r & 7));
                asm volatile("ldmatrix.sync.aligned.m8n8.x4.shared.b16 {%0,%1,%2,%3}, [%4];"
                             : "=r"(a[0]), "=r"(a[1]), "=r"(a[2]), "=r"(a[3])
                             : "r"(addr));
            }
            uint32_t b[4][4];
#pragma unroll
            for (int nt = 0; nt < 4; nt++) {
                int r = b_row + nt * 16;
                uint32_t addr = sBB + r * 128 + 16 * ((ks * 2 + b_jc) ^ (r & 7));
                asm volatile("ldmatrix.sync.aligned.m8n8.x4.shared.b16 {%0,%1,%2,%3}, [%4];"
                             : "=r"(b[nt][0]), "=r"(b[nt][1]), "=r"(b[nt][2]), "=r"(b[nt][3])
                             : "r"(addr));
            }
#pragma unroll
            for (int j = 0; j < 8; j++) {
                uint32_t b0 = b[j >> 1][(j & 1) * 2 + 0];
                uint32_t b1 = b[j >> 1][(j & 1) * 2 + 1];
                asm volatile(
                    "mma.sync.aligned.m16n8k16.row.col.f32.f16.f16.f32 "
                    "{%0,%1,%2,%3}, {%4,%5,%6,%7}, {%8,%9}, {%0,%1,%2,%3};"
                    : "+f"(acc[j][0]), "+f"(acc[j][1]),
                      "+f"(acc[j][2]), "+f"(acc[j][3])
                    : "r"(a[0]), "r"(a[1]), "r"(a[2]), "r"(a[3]),
                      "r"(b0), "r"(b1));
            }
        }

        if (chunk + 3 < 64) {
            issueB(chunk + 3, (chunk + 3) & 3);
            asm volatile("cp.async.commit_group;\n");
        }
    }

    // epilogue: write accumulators + bias
    float bias = biases[0];
    int g = lid >> 2, t = lid & 3;
    {
        int row = r0 + wm + g;
#pragma unroll
        for (int j = 0; j < 8; j++) {
            int col = wn + j * 8 + t * 2;
            float2 v0 = make_float2(acc[j][0] + bias, acc[j][1] + bias);
            float2 v1 = make_float2(acc[j][2] + bias, acc[j][3] + bias);
            *(float2*)(out + (size_t)row * 256 + col)       = v0;
            *(float2*)(out + (size_t)(row + 8) * 256 + col) = v1;
        }
    }
}

// ---------------- launch ----------------
extern "C" void kernel_launch(void* const* d_in, const int* in_sizes, int n_in,
                              void* d_out, int out_size) {
    const float* x      = (const float*)d_in[0];
    const float* beta   = (const float*)d_in[1];
    const float* gamma  = (const float*)d_in[2];
    const float* w      = (const float*)d_in[3];
    const float* biases = (const float*)d_in[4];
    const void*  ci     = d_in[5];
    float* out = (float*)d_out;

    (void)in_sizes; (void)n_in; (void)out_size;

    k_stats<<<64, 512>>>(x);
    k_finalize<<<1, 1024>>>(beta, gamma, ci);
    k_wprep<<<dim3(128, 8), dim3(32, 8)>>>(w);

    cudaFuncSetAttribute(k_gemm, cudaFuncAttributeMaxDynamicSharedMemorySize, GEMM_SMEM);
    k_gemm<<<128, 512, GEMM_SMEM>>>(out, x, biases);
}

// round 14
// speedup vs baseline: 1.3979x; 1.3979x over previous
#include <cuda_runtime.h>
#include <cuda_fp16.h>
#include <cstdint>
#include <math.h>

// Problem dims
#define B_ROWS 8192
#define N_COLS 512
#define M_MIN  1024
#define OUT_N  256
#define K_TOT  4096   // 512*6 + 1024

// ---------------- device scratch (static, no allocation) ----------------
__device__ float g_psum[64 * 512];
__device__ float g_psumsq[64 * 512];
__device__ float g_s[512];
__device__ float g_dq[6 * 512];           // [q][n]  (q=0 base, q=1..5 branches)
__device__ uint32_t g_minidx[M_MIN];      // packed (off2<<16)|off1, off = q*512+n (< 3072)
__device__ __align__(16) __half g_wT[(size_t)OUT_N * K_TOT];   // 2 MB (B^T, [256,4096] K-major, K-permuted)

__constant__ float QCOEF[5] = {-3.0f, -0.834f, -0.248f, 0.248f, 0.834f};

// ---------------- helpers ----------------
__device__ __forceinline__ uint32_t smem_u32(const void* p) {
    uint32_t a;
    asm("{ .reg .u64 t; cvta.to.shared.u64 t, %1; cvt.u32.u64 %0, t; }"
        : "=r"(a) : "l"(p));
    return a;
}

// named barriers (count = 512 = producers 256 + consumers 256)
#define BAR_SYNC(id)   asm volatile("bar.sync %0, 512;"   :: "r"(id) : "memory")
#define BAR_ARRIVE(id) asm volatile("bar.arrive %0, 512;" :: "r"(id) : "memory")
#define FULL0  1
#define EMPTY0 3

// ---------------- stage 1: column statistics (deterministic two-pass) ----------------
__global__ void __launch_bounds__(512) k_stats(const float* __restrict__ x) {
    int col = threadIdx.x;
    int rb  = blockIdx.x * 128;
    const float* xp = x + (size_t)rb * 512 + col;
    float s = 0.f, ss = 0.f;
#pragma unroll 8
    for (int r = 0; r < 128; r++) {
        float v = xp[(size_t)r * 512];
        s += v;
        ss = fmaf(v, v, ss);
    }
    g_psum[blockIdx.x * 512 + col]   = s;
    g_psumsq[blockIdx.x * 512 + col] = ss;
}

// ---------------- stage 2: finalize stats + pack min indices (merged, 1 block) ----------------
// chosen_index may arrive as int64 OR int32 (JAX x64-disabled silently downcasts).
// Column 0 is arange(M): int32-view element 10 == 1 iff int64, == 2 iff int32.
__global__ void __launch_bounds__(1024) k_finalize(const float* __restrict__ beta,
                                                   const float* __restrict__ gamma,
                                                   const void* __restrict__ ci_raw) {
    int tid = threadIdx.x;
    if (tid < 512) {
        int n = tid;
        float s = 0.f, ss = 0.f;
        for (int b = 0; b < 64; b++) {       // fixed order -> deterministic
            s  += g_psum[b * 512 + n];
            ss += g_psumsq[b * 512 + n];
        }
        float mean = s * (1.f / 8192.f);
        float var  = ss * (1.f / 8192.f) - mean * mean;
        float sc   = gamma[n] / sqrtf(var + 0.001f);
        float c    = beta[n] - mean * sc;    // normed = sc*x + c
        g_s[n]  = sc;
        g_dq[n] = c;                          // q = 0 (base relu)
#pragma unroll
        for (int q = 0; q < 5; q++)
            g_dq[(q + 1) * 512 + n] = c + beta[n] - gamma[n] * fmaf(QCOEF[q], var, mean);
    }
    {
        int m = tid;
        const int* p32 = (const int*)ci_raw;
        bool is64 = (p32[10] == 1) && (p32[11] == 0);
        uint32_t n1, q1, n2, q2;
        if (is64) {
            const long long* e = (const long long*)ci_raw + (size_t)m * 5;
            n1 = (uint32_t)e[1]; q1 = (uint32_t)e[2];
            n2 = (uint32_t)e[3]; q2 = (uint32_t)e[4];
        } else {
            const int* e = p32 + (size_t)m * 5;
            n1 = (uint32_t)e[1]; q1 = (uint32_t)e[2];
            n2 = (uint32_t)e[3]; q2 = (uint32_t)e[4];
        }
        g_minidx[m] = ((q2 * 512u + n2) << 16) | (q1 * 512u + n1);
    }
}

// ---------------- stage 3: w -> wT fp16, K-permuted (j = q*512+n for j<3072) ----------------
__global__ void __launch_bounds__(256) k_wprep(const float* __restrict__ w) {
    __shared__ float tile[32][33];
    int j0 = blockIdx.x * 32, o0 = blockIdx.y * 32;
    int tx = threadIdx.x, ty = threadIdx.y;
    for (int i = ty; i < 32; i += 8) {
        int j = j0 + i;
        int k = (j < 3072) ? ((j & 511) * 6 + (j >> 9)) : j;   // back to original row order
        tile[i][tx] = w[(size_t)k * 256 + o0 + tx];
    }
    __syncthreads();
    for (int i = ty; i < 32; i += 8)
        g_wT[(size_t)(o0 + i) * K_TOT + j0 + tx] = __float2half_rn(tile[tx][i]);
}

// ---------------- stage 4: FUSED featgen + GEMM, WARP-SPECIALIZED ----------------
// 512 threads: warps 0-7 = MMA consumers (warp tile 32x64), warps 8-15 = producers
// (A-tile synthesis + all B cp.async). Decoupled via named barriers:
//   full[s]  (id 1+s): producers arrive after slot s ready; consumers sync before reading.
//   empty[s] (id 3+s): consumers arrive after done with slot s; producers sync before reuse.
// A ring depth 2; B ring depth 4 with prefetch distance 2 (reuse always covered by empty).
#define A_SLOT_BYTES  8192                      // 64 rows x 128 B
#define B_STAGE_BYTES 32768                     // 256 rows x 128 B
#define B_OFF   (2 * A_SLOT_BYTES)              // 16384
#define P_OFF   (B_OFF + 4 * B_STAGE_BYTES)     // 147456
#define P_STRIDE 520                            // halfs per p row
#define GEMM_SMEM (P_OFF + 64 * P_STRIDE * 2)   // 214016

__global__ void __launch_bounds__(512, 1) k_gemm(float* __restrict__ out,
                                                 const float* __restrict__ x,
                                                 const float* __restrict__ biases) {
    extern __shared__ __align__(1024) char smem[];
    uint32_t sb = smem_u32(smem);
    __half* p_sh = (__half*)(smem + P_OFF);
    int tid = threadIdx.x, wid = tid >> 5, lid = tid & 31;
    int r0 = blockIdx.x * 64;    // batch-row tile

    // ---- build p[64][512]: p = x * s (fp16), all 512 threads ----
    {
        int grp = tid & 63;        // 8-float group within row
        int rt  = tid >> 6;        // 0..7
        const float4* s4 = (const float4*)(g_s + grp * 8);
        float4 sa4 = s4[0], sb4 = s4[1];
#pragma unroll
        for (int t = 0; t < 8; t++) {
            int row = rt + t * 8;
            const float4* xr = (const float4*)(x + (size_t)(r0 + row) * 512 + grp * 8);
            float4 xa = xr[0], xb = xr[1];
            union { __half2 h[4]; uint4 u; } o;
            o.h[0] = __floats2half2_rn(xa.x * sa4.x, xa.y * sa4.y);
            o.h[1] = __floats2half2_rn(xa.z * sa4.z, xa.w * sa4.w);
            o.h[2] = __floats2half2_rn(xb.x * sb4.x, xb.y * sb4.y);
            o.h[3] = __floats2half2_rn(xb.z * sb4.z, xb.w * sb4.w);
            *(uint4*)(p_sh + row * P_STRIDE + grp * 8) = o.u;
        }
    }
    __syncthreads();

    if (wid >= 8) {
        // ================= PRODUCER warps (tid 256..511) =================
        int ptid = tid - 256;      // 0..255
        const char* Bbase = (const char*)g_wT;

        auto issueB = [&](int chunk, int stage) {
            uint32_t sB = sb + B_OFF + stage * B_STAGE_BYTES;
            const char* Bg = Bbase + chunk * 128;
#pragma unroll
            for (int t = 0; t < 8; t++) {
                int idx = ptid + t * 256;       // 0..2047
                int row = idx >> 3, jj = idx & 7;
                uint32_t off = row * 128 + 16 * (jj ^ (row & 7));
                const char* gb = Bg + (size_t)row * 8192 + jj * 16;
                asm volatile("cp.async.cg.shared.global [%0], [%1], 16;\n"
                             :: "r"(sB + off), "l"(gb));
            }
        };

        auto produceA = [&](int chunk, int slot) {
            char* sa = smem + slot * A_SLOT_BYTES;
#pragma unroll
            for (int h = 0; h < 2; h++) {
                int u = ptid + h * 256;         // 0..511
                int jj = u & 7, arow = u >> 3;
                uint32_t dsto = arow * 128 + 16 * (jj ^ (arow & 7));
                if (chunk < 48) {
                    int q = chunk >> 3;
                    int nc = (chunk & 7) * 64 + jj * 8;
                    const float4* dd = (const float4*)(g_dq + q * 512 + nc);
                    float4 da = dd[0], db = dd[1];
                    const __half2* pr = (const __half2*)(p_sh + arow * P_STRIDE + nc);
                    __half2 h0 = pr[0], h1 = pr[1], h2 = pr[2], h3 = pr[3];
                    float2 f0 = __half22float2(h0), f1 = __half22float2(h1);
                    float2 f2 = __half22float2(h2), f3 = __half22float2(h3);
                    union { __half2 hh[4]; uint4 u4; } o;
                    o.hh[0] = __floats2half2_rn(fmaxf(f0.x + da.x, 0.f), fmaxf(f0.y + da.y, 0.f));
                    o.hh[1] = __floats2half2_rn(fmaxf(f1.x + da.z, 0.f), fmaxf(f1.y + da.w, 0.f));
                    o.hh[2] = __floats2half2_rn(fmaxf(f2.x + db.x, 0.f), fmaxf(f2.y + db.y, 0.f));
                    o.hh[3] = __floats2half2_rn(fmaxf(f3.x + db.z, 0.f), fmaxf(f3.y + db.w, 0.f));
                    *(uint4*)(sa + dsto) = o.u4;
                } else {
                    int m0 = (chunk - 48) * 64 + jj * 8;
                    uint4 pa = *(const uint4*)(g_minidx + m0);
                    uint4 pb = *(const uint4*)(g_minidx + m0 + 4);
                    uint32_t pk[8] = {pa.x, pa.y, pa.z, pa.w, pb.x, pb.y, pb.z, pb.w};
                    const __half* pr = p_sh + arow * P_STRIDE;
                    union { __half2 hh[4]; uint4 u4; } o;
#pragma unroll
                    for (int i = 0; i < 4; i++) {
                        uint32_t wa = pk[2 * i], wb = pk[2 * i + 1];
                        int a1 = wa & 0xFFFF, a2 = wa >> 16;
                        int b1 = wb & 0xFFFF, b2 = wb >> 16;
                        float va = fminf(fmaxf(__half2float(pr[a1 & 511]) + g_dq[a1], 0.f),
                                         fmaxf(__half2float(pr[a2 & 511]) + g_dq[a2], 0.f));
                        float vb = fminf(fmaxf(__half2float(pr[b1 & 511]) + g_dq[b1], 0.f),
                                         fmaxf(__half2float(pr[b2 & 511]) + g_dq[b2], 0.f));
                        o.hh[i] = __floats2half2_rn(va, vb);
                    }
                    *(uint4*)(sa + dsto) = o.u4;
                }
            }
        };

        // prologue: B(0), B(1) in flight
        issueB(0, 0); asm volatile("cp.async.commit_group;\n");
        issueB(1, 1); asm volatile("cp.async.commit_group;\n");

        for (int c = 0; c < 64; c++) {
            if (c >= 2) BAR_SYNC(EMPTY0 + (c & 1));     // consumers done with c-2
            if (c + 2 < 64) issueB(c + 2, (c + 2) & 3); // slot (c+2)&3 freed at c-2
            asm volatile("cp.async.commit_group;\n");   // (empty group when no loads)
            produceA(c, c & 1);
            asm volatile("cp.async.wait_group 2;\n");   // B(c) landed
            asm volatile("membar.cta;" ::: "memory");   // publish STS + cp.async data
            BAR_ARRIVE(FULL0 + (c & 1));
        }
        // producers done; exit (no epilogue work)
    } else {
        // ================= CONSUMER warps (tid 0..255), warp tile 32(M) x 64(N) =================
        int wm = (wid & 1) * 32;
        int wn = (wid >> 1) * 64;

        int l7 = lid & 7, mi = lid >> 3;
        int a_row = wm + (mi & 1) * 8 + l7;
        int a_jc  = mi >> 1;            // 0/1 within k16
        int b_row = wn + (mi >> 1) * 8 + l7;
        int b_jc  = mi & 1;

        float acc[2][8][4];
#pragma unroll
        for (int i = 0; i < 2; i++)
#pragma unroll
            for (int j = 0; j < 8; j++)
#pragma unroll
                for (int k = 0; k < 4; k++) acc[i][j][k] = 0.f;

        for (int c = 0; c < 64; c++) {
            BAR_SYNC(FULL0 + (c & 1));                  // A(c) + B(c) ready

            uint32_t sA  = sb + (c & 1) * A_SLOT_BYTES;
            uint32_t sBB = sb + B_OFF + (c & 3) * B_STAGE_BYTES;

#pragma unroll
            for (int ks = 0; ks < 4; ks++) {            // 4 x k16 per BK=64 chunk
                uint32_t a[2][4];
#pragma unroll
                for (int mt = 0; mt < 2; mt++) {
                    int r = a_row + mt * 16;
                    uint32_t addr = sA + r * 128 + 16 * ((ks * 2 + a_jc) ^ (r & 7));
                    asm volatile("ldmatrix.sync.aligned.m8n8.x4.shared.b16 {%0,%1,%2,%3}, [%4];"
                                 : "=r"(a[mt][0]), "=r"(a[mt][1]), "=r"(a[mt][2]), "=r"(a[mt][3])
                                 : "r"(addr));
                }
                uint32_t b[4][4];
#pragma unroll
                for (int nt = 0; nt < 4; nt++) {
                    int r = b_row + nt * 16;
                    uint32_t addr = sBB + r * 128 + 16 * ((ks * 2 + b_jc) ^ (r & 7));
                    asm volatile("ldmatrix.sync.aligned.m8n8.x4.shared.b16 {%0,%1,%2,%3}, [%4];"
                                 : "=r"(b[nt][0]), "=r"(b[nt][1]), "=r"(b[nt][2]), "=r"(b[nt][3])
                                 : "r"(addr));
                }
#pragma unroll
                for (int mt = 0; mt < 2; mt++) {
#pragma unroll
                    for (int j = 0; j < 8; j++) {
                        uint32_t b0 = b[j >> 1][(j & 1) * 2 + 0];
                        uint32_t b1 = b[j >> 1][(j & 1) * 2 + 1];
                        asm volatile(
                            "mma.sync.aligned.m16n8k16.row.col.f32.f16.f16.f32 "
                            "{%0,%1,%2,%3}, {%4,%5,%6,%7}, {%8,%9}, {%0,%1,%2,%3};"
                            : "+f"(acc[mt][j][0]), "+f"(acc[mt][j][1]),
                              "+f"(acc[mt][j][2]), "+f"(acc[mt][j][3])
                            : "r"(a[mt][0]), "r"(a[mt][1]), "r"(a[mt][2]), "r"(a[mt][3]),
                              "r"(b0), "r"(b1));
                    }
                }
            }

            BAR_ARRIVE(EMPTY0 + (c & 1));               // slot c&1 free for c+2
        }

        // epilogue: write accumulators + bias
        float bias = biases[0];
        int g = lid >> 2, t = lid & 3;
#pragma unroll
        for (int mt = 0; mt < 2; mt++) {
            int row = r0 + wm + mt * 16 + g;
#pragma unroll
            for (int j = 0; j < 8; j++) {
                int col = wn + j * 8 + t * 2;
                float2 v0 = make_float2(acc[mt][j][0] + bias, acc[mt][j][1] + bias);
                float2 v1 = make_float2(acc[mt][j][2] + bias, acc[mt][j][3] + bias);
                *(float2*)(out + (size_t)row * 256 + col)       = v0;
                *(float2*)(out + (size_t)(row + 8) * 256 + col) = v1;
            }
        }
    }
}

// ---------------- launch ----------------
extern "C" void kernel_launch(void* const* d_in, const int* in_sizes, int n_in,
                              void* d_out, int out_size) {
    const float* x      = (const float*)d_in[0];
    const float* beta   = (const float*)d_in[1];
    const float* gamma  = (const float*)d_in[2];
    const float* w      = (const float*)d_in[3];
    const float* biases = (const float*)d_in[4];
    const void*  ci     = d_in[5];
    float* out = (float*)d_out;

    (void)in_sizes; (void)n_in; (void)out_size;

    k_stats<<<64, 512>>>(x);
    k_finalize<<<1, 1024>>>(beta, gamma, ci);
    k_wprep<<<dim3(128, 8), dim3(32, 8)>>>(w);

    cudaFuncSetAttribute(k_gemm, cudaFuncAttributeMaxDynamicSharedMemorySize, GEMM_SMEM);
    k_gemm<<<128, 512, GEMM_SMEM>>>(out, x, biases);
}

// round 15
// speedup vs baseline: 1.4268x; 1.0206x over previous
#include <cuda_runtime.h>
#include <cuda_fp16.h>
#include <cstdint>
#include <math.h>

// Problem dims
#define B_ROWS 8192
#define N_COLS 512
#define M_MIN  1024
#define OUT_N  256
#define K_TOT  4096   // 512*6 + 1024

// ---------------- device scratch (static, no allocation) ----------------
__device__ float g_psum[64 * 512];
__device__ float g_psumsq[64 * 512];
__device__ float g_s[512];
__device__ float g_dq[6 * 512];           // [q][n]  (q=0 base, q=1..5 branches)
__device__ uint32_t g_minidx[M_MIN];      // packed (off2<<16)|off1, off = q*512+n (< 3072)
__device__ __align__(16) __half g_wT[(size_t)OUT_N * K_TOT];   // 2 MB (B^T, [256,4096] K-major, K-permuted)

__constant__ float QCOEF[5] = {-3.0f, -0.834f, -0.248f, 0.248f, 0.834f};

// ---------------- helpers ----------------
__device__ __forceinline__ uint32_t smem_u32(const void* p) {
    uint32_t a;
    asm("{ .reg .u64 t; cvta.to.shared.u64 t, %1; cvt.u32.u64 %0, t; }"
        : "=r"(a) : "l"(p));
    return a;
}

// named barriers (count = 512 = producers 256 + consumers 256)
// bar.arrive = release, bar.sync = acquire (CTA scope) -> STS before arrive is
// visible after the matching sync; cp.async data is visible after wait_group in
// the issuing thread, then published by the same release/acquire pair.
#define BAR_SYNC(id)   asm volatile("bar.sync %0, 512;"   :: "r"(id) : "memory")
#define BAR_ARRIVE(id) asm volatile("bar.arrive %0, 512;" :: "r"(id) : "memory")
#define FULL0  1
#define EMPTY0 3

// ---------------- stage 1: column statistics (deterministic two-pass) ----------------
__global__ void __launch_bounds__(512) k_stats(const float* __restrict__ x) {
    int col = threadIdx.x;
    int rb  = blockIdx.x * 128;
    const float* xp = x + (size_t)rb * 512 + col;
    float s = 0.f, ss = 0.f;
#pragma unroll 8
    for (int r = 0; r < 128; r++) {
        float v = xp[(size_t)r * 512];
        s += v;
        ss = fmaf(v, v, ss);
    }
    g_psum[blockIdx.x * 512 + col]   = s;
    g_psumsq[blockIdx.x * 512 + col] = ss;
}

// ---------------- stage 2: finalize stats + pack min indices (merged, 1 block) ----------------
// chosen_index may arrive as int64 OR int32 (JAX x64-disabled silently downcasts).
// Column 0 is arange(M): int32-view element 10 == 1 iff int64, == 2 iff int32.
__global__ void __launch_bounds__(1024) k_finalize(const float* __restrict__ beta,
                                                   const float* __restrict__ gamma,
                                                   const void* __restrict__ ci_raw) {
    int tid = threadIdx.x;
    if (tid < 512) {
        int n = tid;
        float s = 0.f, ss = 0.f;
        for (int b = 0; b < 64; b++) {       // fixed order -> deterministic
            s  += g_psum[b * 512 + n];
            ss += g_psumsq[b * 512 + n];
        }
        float mean = s * (1.f / 8192.f);
        float var  = ss * (1.f / 8192.f) - mean * mean;
        float sc   = gamma[n] / sqrtf(var + 0.001f);
        float c    = beta[n] - mean * sc;    // normed = sc*x + c
        g_s[n]  = sc;
        g_dq[n] = c;                          // q = 0 (base relu)
#pragma unroll
        for (int q = 0; q < 5; q++)
            g_dq[(q + 1) * 512 + n] = c + beta[n] - gamma[n] * fmaf(QCOEF[q], var, mean);
    }
    {
        int m = tid;
        const int* p32 = (const int*)ci_raw;
        bool is64 = (p32[10] == 1) && (p32[11] == 0);
        uint32_t n1, q1, n2, q2;
        if (is64) {
            const long long* e = (const long long*)ci_raw + (size_t)m * 5;
            n1 = (uint32_t)e[1]; q1 = (uint32_t)e[2];
            n2 = (uint32_t)e[3]; q2 = (uint32_t)e[4];
        } else {
            const int* e = p32 + (size_t)m * 5;
            n1 = (uint32_t)e[1]; q1 = (uint32_t)e[2];
            n2 = (uint32_t)e[3]; q2 = (uint32_t)e[4];
        }
        g_minidx[m] = ((q2 * 512u + n2) << 16) | (q1 * 512u + n1);
    }
}

// ---------------- stage 3: w -> wT fp16, K-permuted (j = q*512+n for j<3072) ----------------
__global__ void __launch_bounds__(256) k_wprep(const float* __restrict__ w) {
    __shared__ float tile[32][33];
    int j0 = blockIdx.x * 32, o0 = blockIdx.y * 32;
    int tx = threadIdx.x, ty = threadIdx.y;
    for (int i = ty; i < 32; i += 8) {
        int j = j0 + i;
        int k = (j < 3072) ? ((j & 511) * 6 + (j >> 9)) : j;   // back to original row order
        tile[i][tx] = w[(size_t)k * 256 + o0 + tx];
    }
    __syncthreads();
    for (int i = ty; i < 32; i += 8)
        g_wT[(size_t)(o0 + i) * K_TOT + j0 + tx] = __float2half_rn(tile[tx][i]);
}

// ---------------- stage 4: FUSED featgen + GEMM, WARP-SPECIALIZED ----------------
// 512 threads: warps 0-7 = MMA consumers (warp tile 32x64), warps 8-15 = producers
// (A-tile synthesis + all B cp.async). Named-barrier handshake (release/acquire).
// A ring depth 2; B ring depth 4 with prefetch distance 2. g_dq staged in smem.
#define A_SLOT_BYTES  8192                      // 64 rows x 128 B
#define B_STAGE_BYTES 32768                     // 256 rows x 128 B
#define B_OFF   (2 * A_SLOT_BYTES)              // 16384
#define P_OFF   (B_OFF + 4 * B_STAGE_BYTES)     // 147456
#define P_STRIDE 520                            // halfs per p row
#define DQ_OFF  (P_OFF + 64 * P_STRIDE * 2)     // 214016
#define GEMM_SMEM (DQ_OFF + 6 * 512 * 4)        // 226304

__global__ void __launch_bounds__(512, 1) k_gemm(float* __restrict__ out,
                                                 const float* __restrict__ x,
                                                 const float* __restrict__ biases) {
    extern __shared__ __align__(1024) char smem[];
    uint32_t sb = smem_u32(smem);
    __half* p_sh = (__half*)(smem + P_OFF);
    float* dq_sh = (float*)(smem + DQ_OFF);
    int tid = threadIdx.x, wid = tid >> 5, lid = tid & 31;
    int r0 = blockIdx.x * 64;    // batch-row tile

    // ---- stage g_dq into smem (3072 floats) ----
    for (int i = tid; i < 3072; i += 512)
        dq_sh[i] = g_dq[i];

    // ---- build p[64][512]: p = x * s (fp16), all 512 threads ----
    {
        int grp = tid & 63;        // 8-float group within row
        int rt  = tid >> 6;        // 0..7
        const float4* s4 = (const float4*)(g_s + grp * 8);
        float4 sa4 = s4[0], sb4 = s4[1];
#pragma unroll
        for (int t = 0; t < 8; t++) {
            int row = rt + t * 8;
            const float4* xr = (const float4*)(x + (size_t)(r0 + row) * 512 + grp * 8);
            float4 xa = xr[0], xb = xr[1];
            union { __half2 h[4]; uint4 u; } o;
            o.h[0] = __floats2half2_rn(xa.x * sa4.x, xa.y * sa4.y);
            o.h[1] = __floats2half2_rn(xa.z * sa4.z, xa.w * sa4.w);
            o.h[2] = __floats2half2_rn(xb.x * sb4.x, xb.y * sb4.y);
            o.h[3] = __floats2half2_rn(xb.z * sb4.z, xb.w * sb4.w);
            *(uint4*)(p_sh + row * P_STRIDE + grp * 8) = o.u;
        }
    }
    __syncthreads();

    if (wid >= 8) {
        // ================= PRODUCER warps (tid 256..511) =================
        int ptid = tid - 256;      // 0..255
        const char* Bbase = (const char*)g_wT;

        auto issueB = [&](int chunk, int stage) {
            uint32_t sB = sb + B_OFF + stage * B_STAGE_BYTES;
            const char* Bg = Bbase + chunk * 128;
#pragma unroll
            for (int t = 0; t < 8; t++) {
                int idx = ptid + t * 256;       // 0..2047
                int row = idx >> 3, jj = idx & 7;
                uint32_t off = row * 128 + 16 * (jj ^ (row & 7));
                const char* gb = Bg + (size_t)row * 8192 + jj * 16;
                asm volatile("cp.async.cg.shared.global [%0], [%1], 16;\n"
                             :: "r"(sB + off), "l"(gb));
            }
        };

        auto produceA = [&](int chunk, int slot) {
            char* sa = smem + slot * A_SLOT_BYTES;
#pragma unroll
            for (int h = 0; h < 2; h++) {
                int u = ptid + h * 256;         // 0..511
                int jj = u & 7, arow = u >> 3;
                uint32_t dsto = arow * 128 + 16 * (jj ^ (arow & 7));
                if (chunk < 48) {
                    int q = chunk >> 3;
                    int nc = (chunk & 7) * 64 + jj * 8;
                    const float4* dd = (const float4*)(dq_sh + q * 512 + nc);
                    float4 da = dd[0], db = dd[1];
                    const __half2* pr = (const __half2*)(p_sh + arow * P_STRIDE + nc);
                    __half2 h0 = pr[0], h1 = pr[1], h2 = pr[2], h3 = pr[3];
                    float2 f0 = __half22float2(h0), f1 = __half22float2(h1);
                    float2 f2 = __half22float2(h2), f3 = __half22float2(h3);
                    union { __half2 hh[4]; uint4 u4; } o;
                    o.hh[0] = __floats2half2_rn(fmaxf(f0.x + da.x, 0.f), fmaxf(f0.y + da.y, 0.f));
                    o.hh[1] = __floats2half2_rn(fmaxf(f1.x + da.z, 0.f), fmaxf(f1.y + da.w, 0.f));
                    o.hh[2] = __floats2half2_rn(fmaxf(f2.x + db.x, 0.f), fmaxf(f2.y + db.y, 0.f));
                    o.hh[3] = __floats2half2_rn(fmaxf(f3.x + db.z, 0.f), fmaxf(f3.y + db.w, 0.f));
                    *(uint4*)(sa + dsto) = o.u4;
                } else {
                    int m0 = (chunk - 48) * 64 + jj * 8;
                    uint4 pa = *(const uint4*)(g_minidx + m0);
                    uint4 pb = *(const uint4*)(g_minidx + m0 + 4);
                    uint32_t pk[8] = {pa.x, pa.y, pa.z, pa.w, pb.x, pb.y, pb.z, pb.w};
                    const __half* pr = p_sh + arow * P_STRIDE;
                    union { __half2 hh[4]; uint4 u4; } o;
#pragma unroll
                    for (int i = 0; i < 4; i++) {
                        uint32_t wa = pk[2 * i], wb = pk[2 * i + 1];
                        int a1 = wa & 0xFFFF, a2 = wa >> 16;
                        int b1 = wb & 0xFFFF, b2 = wb >> 16;
                        float va = fminf(fmaxf(__half2float(pr[a1 & 511]) + dq_sh[a1], 0.f),
                                         fmaxf(__half2float(pr[a2 & 511]) + dq_sh[a2], 0.f));
                        float vb = fminf(fmaxf(__half2float(pr[b1 & 511]) + dq_sh[b1], 0.f),
                                         fmaxf(__half2float(pr[b2 & 511]) + dq_sh[b2], 0.f));
                        o.hh[i] = __floats2half2_rn(va, vb);
                    }
                    *(uint4*)(sa + dsto) = o.u4;
                }
            }
        };

        // prologue: B(0), B(1) in flight
        issueB(0, 0); asm volatile("cp.async.commit_group;\n");
        issueB(1, 1); asm volatile("cp.async.commit_group;\n");

        for (int c = 0; c < 64; c++) {
            if (c >= 2) BAR_SYNC(EMPTY0 + (c & 1));     // consumers done with c-2
            if (c + 2 < 64) issueB(c + 2, (c + 2) & 3); // slot (c+2)&3 freed at c-2
            asm volatile("cp.async.commit_group;\n");   // (empty group when no loads; keeps wait_group count)
            produceA(c, c & 1);
            asm volatile("cp.async.wait_group 2;\n");   // B(c) landed (visible to this thread)
            BAR_ARRIVE(FULL0 + (c & 1));                // release: publishes STS + waited cp.async
        }
        // producers done; exit (no epilogue work)
    } else {
        // ================= CONSUMER warps (tid 0..255), warp tile 32(M) x 64(N) =================
        int wm = (wid & 1) * 32;
        int wn = (wid >> 1) * 64;

        int l7 = lid & 7, mi = lid >> 3;
        int a_row = wm + (mi & 1) * 8 + l7;
        int a_jc  = mi >> 1;            // 0/1 within k16
        int b_row = wn + (mi >> 1) * 8 + l7;
        int b_jc  = mi & 1;

        float acc[2][8][4];
#pragma unroll
        for (int i = 0; i < 2; i++)
#pragma unroll
            for (int j = 0; j < 8; j++)
#pragma unroll
                for (int k = 0; k < 4; k++) acc[i][j][k] = 0.f;

        for (int c = 0; c < 64; c++) {
            BAR_SYNC(FULL0 + (c & 1));                  // acquire: A(c) + B(c) ready

            uint32_t sA  = sb + (c & 1) * A_SLOT_BYTES;
            uint32_t sBB = sb + B_OFF + (c & 3) * B_STAGE_BYTES;

#pragma unroll
            for (int ks = 0; ks < 4; ks++) {            // 4 x k16 per BK=64 chunk
                uint32_t a[2][4];
#pragma unroll
                for (int mt = 0; mt < 2; mt++) {
                    int r = a_row + mt * 16;
                    uint32_t addr = sA + r * 128 + 16 * ((ks * 2 + a_jc) ^ (r & 7));
                    asm volatile("ldmatrix.sync.aligned.m8n8.x4.shared.b16 {%0,%1,%2,%3}, [%4];"
                                 : "=r"(a[mt][0]), "=r"(a[mt][1]), "=r"(a[mt][2]), "=r"(a[mt][3])
                                 : "r"(addr));
                }
                uint32_t b[4][4];
#pragma unroll
                for (int nt = 0; nt < 4; nt++) {
                    int r = b_row + nt * 16;
                    uint32_t addr = sBB + r * 128 + 16 * ((ks * 2 + b_jc) ^ (r & 7));
                    asm volatile("ldmatrix.sync.aligned.m8n8.x4.shared.b16 {%0,%1,%2,%3}, [%4];"
                                 : "=r"(b[nt][0]), "=r"(b[nt][1]), "=r"(b[nt][2]), "=r"(b[nt][3])
                                 : "r"(addr));
                }
#pragma unroll
                for (int mt = 0; mt < 2; mt++) {
#pragma unroll
                    for (int j = 0; j < 8; j++) {
                        uint32_t b0 = b[j >> 1][(j & 1) * 2 + 0];
                        uint32_t b1 = b[j >> 1][(j & 1) * 2 + 1];
                        asm volatile(
                            "mma.sync.aligned.m16n8k16.row.col.f32.f16.f16.f32 "
                            "{%0,%1,%2,%3}, {%4,%5,%6,%7}, {%8,%9}, {%0,%1,%2,%3};"
                            : "+f"(acc[mt][j][0]), "+f"(acc[mt][j][1]),
                              "+f"(acc[mt][j][2]), "+f"(acc[mt][j][3])
                            : "r"(a[mt][0]), "r"(a[mt][1]), "r"(a[mt][2]), "r"(a[mt][3]),
                              "r"(b0), "r"(b1));
                    }
                }
            }

            BAR_ARRIVE(EMPTY0 + (c & 1));               // slot c&1 free for c+2
        }

        // epilogue: write accumulators + bias
        float bias = biases[0];
        int g = lid >> 2, t = lid & 3;
#pragma unroll
        for (int mt = 0; mt < 2; mt++) {
            int row = r0 + wm + mt * 16 + g;
#pragma unroll
            for (int j = 0; j < 8; j++) {
                int col = wn + j * 8 + t * 2;
                float2 v0 = make_float2(acc[mt][j][0] + bias, acc[mt][j][1] + bias);
                float2 v1 = make_float2(acc[mt][j][2] + bias, acc[mt][j][3] + bias);
                *(float2*)(out + (size_t)row * 256 + col)       = v0;
                *(float2*)(out + (size_t)(row + 8) * 256 + col) = v1;
            }
        }
    }
}

// ---------------- launch ----------------
extern "C" void kernel_launch(void* const* d_in, const int* in_sizes, int n_in,
                              void* d_out, int out_size) {
    const float* x      = (const float*)d_in[0];
    const float* beta   = (const float*)d_in[1];
    const float* gamma  = (const float*)d_in[2];
    const float* w      = (const float*)d_in[3];
    const float* biases = (const float*)d_in[4];
    const void*  ci     = d_in[5];
    float* out = (float*)d_out;

    (void)in_sizes; (void)n_in; (void)out_size;

    k_stats<<<64, 512>>>(x);
    k_finalize<<<1, 1024>>>(beta, gamma, ci);
    k_wprep<<<dim3(128, 8), dim3(32, 8)>>>(w);

    cudaFuncSetAttribute(k_gemm, cudaFuncAttributeMaxDynamicSharedMemorySize, GEMM_SMEM);
    k_gemm<<<128, 512, GEMM_SMEM>>>(out, x, biases);
}